// round 15
// baseline (speedup 1.0000x reference)
#include <cuda_runtime.h>
#include <math.h>
#include <stdint.h>

// Problem constants
#define B 128
#define L 512
#define H 512
#define V 50000

#define NBLK 128
#define NTHR 512

typedef unsigned long long ull;

// ---------------------------------------------------------------------------
// Device globals (static scratch; no runtime allocation)
// ---------------------------------------------------------------------------
__device__ float    g_hT[2][H * B];       // transposed hidden state [k][b], x2
__device__ float    g_c[B * H];           // cell state (segment handoff)
__device__ int      g_tokT[L * B];        // transposed tokens [t][b]
__device__ unsigned g_arrive;             // grid barrier counter
__device__ float    g_xp[(long)L * 2048 * B];  // x_proj + biases: [t][grow][b]

// ---------------------------------------------------------------------------
__device__ __forceinline__ float2 unpackf2(ull v) {
    float2 r; asm("mov.b64 {%0, %1}, %2;" : "=f"(r.x), "=f"(r.y) : "l"(v));
    return r;
}
__device__ __forceinline__ void fma2(ull& d, ull a, ull b) {
    asm("fma.rn.f32x2 %0, %1, %2, %0;" : "+l"(d) : "l"(a), "l"(b));
}
__device__ __forceinline__ float sigf(float x) {
    return 1.f / (1.f + __expf(-x));
}

// ---------------------------------------------------------------------------
__global__ void k_init(const int* __restrict__ tokens) {
    int i = blockIdx.x * blockDim.x + threadIdx.x;
    if (i < H * B) { g_hT[0][i] = 0.f; g_hT[1][i] = 0.f; g_c[i] = 0.f; }
    if (i < L * B) {
        int t = i >> 7, b = i & 127;
        g_tokT[i] = tokens[b * L + t];
    }
    if (i == 0) g_arrive = 0u;
}

// ---------------------------------------------------------------------------
// x_proj GEMM: g_xp[t][grow][b] = Wih[grow,:].emb[tok[t][b],:] + bih + bhh
// A staged as pre-duplicated (a,a) pairs -> no packf2 MOVs in the inner loop:
// per k: 4 LDS.128 (A-dup) + 2 LDS.128 (B) + 32 fma2.
// ---------------------------------------------------------------------------
__global__ void __launch_bounds__(256, 2)
k_xproj(const float* __restrict__ Wih, const float* __restrict__ bih,
        const float* __restrict__ bhh, const float* __restrict__ emb)
{
    __shared__ float As2[16 * 264];   // dup pairs: row k holds 128*(a,a)
    __shared__ float Bs[16 * 132];
    __shared__ float bsum[128];
    __shared__ int   tok[128];

    const int gt  = blockIdx.x;     // grow tile 0..15
    const int t   = blockIdx.y;     // timestep 0..511
    const int tid = threadIdx.x;
    const int ty  = tid >> 4;
    const int tx  = tid & 15;

    if (tid < 128) {
        tok[tid]  = g_tokT[t * 128 + tid];
        int grow  = gt * 128 + tid;
        bsum[tid] = bih[grow] + bhh[grow];
    }
    __syncthreads();

    ull acc[8][4];
    #pragma unroll
    for (int i = 0; i < 8; i++)
        #pragma unroll
        for (int j = 0; j < 4; j++) acc[i][j] = 0ull;

    for (int k0 = 0; k0 < 512; k0 += 16) {
        // stage A (dup pairs): 128 grows x 16 k
        #pragma unroll
        for (int i = 0; i < 2; i++) {
            int idx = tid + 256 * i;
            int r = idx >> 2, f = idx & 3;
            float4 w4 = *(const float4*)(Wih + (gt * 128 + r) * 512 + k0 + 4 * f);
            *(float2*)(As2 + (4 * f + 0) * 264 + 2 * r) = make_float2(w4.x, w4.x);
            *(float2*)(As2 + (4 * f + 1) * 264 + 2 * r) = make_float2(w4.y, w4.y);
            *(float2*)(As2 + (4 * f + 2) * 264 + 2 * r) = make_float2(w4.z, w4.z);
            *(float2*)(As2 + (4 * f + 3) * 264 + 2 * r) = make_float2(w4.w, w4.w);
        }
        // stage B: 128 b x 16 k (embedding gather)
        #pragma unroll
        for (int i = 0; i < 2; i++) {
            int idx = tid + 256 * i;
            int b = idx >> 2, f = idx & 3;
            float4 v4 = *(const float4*)(emb + (long)tok[b] * 512 + k0 + 4 * f);
            Bs[(4 * f + 0) * 132 + b] = v4.x;
            Bs[(4 * f + 1) * 132 + b] = v4.y;
            Bs[(4 * f + 2) * 132 + b] = v4.z;
            Bs[(4 * f + 3) * 132 + b] = v4.w;
        }
        __syncthreads();

        #pragma unroll
        for (int k = 0; k < 16; k++) {
            ulonglong2 a01 = *(const ulonglong2*)(As2 + k * 264 + ty * 16);
            ulonglong2 a23 = *(const ulonglong2*)(As2 + k * 264 + ty * 16 + 4);
            ulonglong2 a45 = *(const ulonglong2*)(As2 + k * 264 + ty * 16 + 8);
            ulonglong2 a67 = *(const ulonglong2*)(As2 + k * 264 + ty * 16 + 12);
            ulonglong2 b01 = *(const ulonglong2*)(Bs + k * 132 + tx * 8);
            ulonglong2 b23 = *(const ulonglong2*)(Bs + k * 132 + tx * 8 + 4);
            ull ad[8] = {a01.x, a01.y, a23.x, a23.y, a45.x, a45.y, a67.x, a67.y};
            #pragma unroll
            for (int i = 0; i < 8; i++) {
                fma2(acc[i][0], ad[i], b01.x);
                fma2(acc[i][1], ad[i], b01.y);
                fma2(acc[i][2], ad[i], b23.x);
                fma2(acc[i][3], ad[i], b23.y);
            }
        }
        __syncthreads();
    }

    float* outp = g_xp + (long)t * 262144 + (gt * 128) * 128;
    #pragma unroll
    for (int i = 0; i < 8; i++) {
        int r = ty * 8 + i;
        float bias = bsum[r];
        float2 p0 = unpackf2(acc[i][0]), p1 = unpackf2(acc[i][1]);
        float2 p2 = unpackf2(acc[i][2]), p3 = unpackf2(acc[i][3]);
        float4 o0 = make_float4(p0.x + bias, p0.y + bias, p1.x + bias, p1.y + bias);
        float4 o1 = make_float4(p2.x + bias, p2.y + bias, p3.x + bias, p3.y + bias);
        *(float4*)(outp + r * 128 + tx * 8)     = o0;
        *(float4*)(outp + r * 128 + tx * 8 + 4) = o1;
    }
}

// ---------------------------------------------------------------------------
// Persistent LSTM recurrence over t in [t0, t1). K = 512 (h half only).
// Block bx owns h-cols [4bx,4bx+4) -> 16 gate rows; dup-weight table in smem.
// 16 warps = 8 K-sets (64 k) x 2 batch-halves (64 b). Thread tile 4r x 8b:
// per k: 2 LDS.128(a) + 2 LDS.128(dup w) + 16 fma2 (half the LDS/FMA of the
// R13 tile). Staging: ldcg LDG.128 -> STS.128, double-buffered 8-k chunks,
// 64-thread set barriers. Grid barrier: cg-style (tid0 fence+atomic+poll),
// with next step's x_proj prefetch issued before the arrive.
// ---------------------------------------------------------------------------
extern __shared__ float smem[];

__global__ void __launch_bounds__(NTHR, 1)
k_lstm(const int* __restrict__ lengths, const float* __restrict__ Whh,
       int t0, int t1)
{
    float* Wd = smem;                  // [512][32] dup (w,w) pairs = 16384 fl
    float* As = Wd + 16384;            // [8 sets][2 buf][8 k][132]
    float* Gs = As + 8 * 2 * 8 * 132;  // [8 sets][16][132] partials

    const int tid  = threadIdx.x;
    const int bx   = blockIdx.x;
    const int w    = tid >> 5;
    const int lane = tid & 31;

    // ---- dup-weight table (W_hh only, K=512) ----
    for (int idx = tid; idx < 16 * 512; idx += NTHR) {
        int k  = idx >> 4;
        int lr = idx & 15;
        int g = lr >> 2, cc = lr & 3;
        int grow = g * 512 + bx * 4 + cc;
        float wv = Whh[grow * 512 + k];
        Wd[k * 32 + 2 * lr]     = wv;
        Wd[k * 32 + 2 * lr + 1] = wv;
    }

    // ---- warp roles ----
    const int set  = w >> 1;           // 0..7: k in [64set, 64set+64)
    const int half = w & 1;            // batch half: b in [64half, 64half+64)
    const int kb0  = 64 * set;
    float* AsS = As + set * (2 * 8 * 132);

    const int rq = lane >> 3;          // 0..3: rows 4rq..4rq+3
    const int bq = lane & 7;           // 0..7: 8-batch oct within half

    // ---- pointwise roles ----
    const int pb = tid >> 2;           // batch 0..127
    const int pc = tid & 3;
    const int hcol = bx * 4 + pc;
    const int len  = lengths[pb];
    float c_reg = g_c[pb * H + hcol];
    float h_reg = g_hT[t0 & 1][hcol * 128 + pb];

    __syncthreads();

    // preload x_proj for step t0
    float xq[4];
    #pragma unroll
    for (int g = 0; g < 4; g++)
        xq[g] = __ldg(g_xp + (long)t0 * 262144
                      + (g * 512 + bx * 4 + pc) * 128 + pb);

    for (int t = t0; t < t1; t++) {
        const int rb = t & 1, wb = rb ^ 1;
        const float* __restrict__ hT = g_hT[rb];

        ull acc[4][4];
        #pragma unroll
        for (int i = 0; i < 4; i++)
            #pragma unroll
            for (int j = 0; j < 4; j++) acc[i][j] = 0ull;

        float4 v4[4];

        // ---- stage chunk 0: warp stages k-rows {kb0 + 4*half + m} ----
        #pragma unroll
        for (int m = 0; m < 4; m++) {
            int kg = kb0 + 4 * half + m;
            v4[m] = __ldcg((const float4*)(hT + kg * 128 + 4 * lane));
        }
        #pragma unroll
        for (int m = 0; m < 4; m++)
            *(float4*)(AsS + (4 * half + m) * 132 + 4 * lane) = v4[m];
        asm volatile("bar.sync %0, %1;" :: "r"(1 + set), "r"(64) : "memory");

        for (int c = 0; c < 8; c++) {
            // prefetch chunk c+1
            if (c < 7) {
                #pragma unroll
                for (int m = 0; m < 4; m++) {
                    int kg = kb0 + 8 * (c + 1) + 4 * half + m;
                    v4[m] = __ldcg((const float4*)(hT + kg * 128 + 4 * lane));
                }
            }

            // compute chunk c (8 k): 4 LDS.128 + 16 fma2 per k
            {
                const float* Ab = AsS + (c & 1) * (8 * 132)
                                + 64 * half + 8 * bq;
                const float* Wk = Wd + (kb0 + 8 * c) * 32 + 8 * rq;
                #pragma unroll
                for (int k = 0; k < 8; k++) {
                    ulonglong2 a01 = *(const ulonglong2*)(Ab + k * 132);
                    ulonglong2 a23 = *(const ulonglong2*)(Ab + k * 132 + 4);
                    ulonglong2 w01 = *(const ulonglong2*)(Wk + k * 32);
                    ulonglong2 w23 = *(const ulonglong2*)(Wk + k * 32 + 4);
                    fma2(acc[0][0], a01.x, w01.x);
                    fma2(acc[0][1], a01.y, w01.x);
                    fma2(acc[0][2], a23.x, w01.x);
                    fma2(acc[0][3], a23.y, w01.x);
                    fma2(acc[1][0], a01.x, w01.y);
                    fma2(acc[1][1], a01.y, w01.y);
                    fma2(acc[1][2], a23.x, w01.y);
                    fma2(acc[1][3], a23.y, w01.y);
                    fma2(acc[2][0], a01.x, w23.x);
                    fma2(acc[2][1], a01.y, w23.x);
                    fma2(acc[2][2], a23.x, w23.x);
                    fma2(acc[2][3], a23.y, w23.x);
                    fma2(acc[3][0], a01.x, w23.y);
                    fma2(acc[3][1], a01.y, w23.y);
                    fma2(acc[3][2], a23.x, w23.y);
                    fma2(acc[3][3], a23.y, w23.y);
                }
            }

            // commit prefetched chunk
            if (c < 7) {
                float* dst = AsS + ((c + 1) & 1) * (8 * 132);
                #pragma unroll
                for (int m = 0; m < 4; m++)
                    *(float4*)(dst + (4 * half + m) * 132 + 4 * lane) = v4[m];
            }
            asm volatile("bar.sync %0, %1;" :: "r"(1 + set), "r"(64) : "memory");
        }

        // ---- park partial tiles: Gs[set][row][b] ----
        #pragma unroll
        for (int r = 0; r < 4; r++) {
            float* gp = Gs + set * (16 * 132) + (4 * rq + r) * 132
                      + 64 * half + 8 * bq;
            ulonglong2 p0; p0.x = acc[r][0]; p0.y = acc[r][1];
            ulonglong2 p1; p1.x = acc[r][2]; p1.y = acc[r][3];
            *(ulonglong2*)(gp)     = p0;
            *(ulonglong2*)(gp + 4) = p1;
        }
        __syncthreads();

        // ---- reduce 8 K-set partials + x_proj + gates ----
        {
            float xi = xq[0], xf = xq[1], xg = xq[2], xo = xq[3];
            #pragma unroll
            for (int s = 0; s < 8; s++) {
                const float* P = Gs + s * (16 * 132);
                xi += P[(0 + pc)  * 132 + pb];
                xf += P[(4 + pc)  * 132 + pb];
                xg += P[(8 + pc)  * 132 + pb];
                xo += P[(12 + pc) * 132 + pb];
            }
            if (t < len) {
                float ig = sigf(xi), fg = sigf(xf), og = sigf(xo);
                float gg = 2.f * sigf(2.f * xg) - 1.f;
                c_reg = fg * c_reg + ig * gg;
                h_reg = og * (2.f * sigf(2.f * c_reg) - 1.f);
            }
            __stcg(&g_hT[wb][hcol * 128 + pb], h_reg);
        }

        // ---- prefetch next step's x_proj BEFORE the barrier ----
        if (t + 1 < t1) {
            #pragma unroll
            for (int g = 0; g < 4; g++)
                xq[g] = __ldg(g_xp + (long)(t + 1) * 262144
                              + (g * 512 + bx * 4 + pc) * 128 + pb);
        }

        // ---- grid barrier: cg-style, tid0 only ----
        __syncthreads();
        if (tid == 0) {
            asm volatile("fence.acq_rel.gpu;" ::: "memory");
            atomicAdd(&g_arrive, 1u);
            unsigned target = (unsigned)NBLK * (unsigned)(t + 1);
            unsigned cur;
            do {
                asm volatile("ld.acquire.gpu.global.u32 %0, [%1];"
                             : "=r"(cur) : "l"(&g_arrive));
            } while (cur < target);
        }
        __syncthreads();
    }

    // ---- segment handoff ----
    g_c[pb * H + hcol] = c_reg;
}

// ---------------------------------------------------------------------------
// FC: out[b, v] = h_final[b, :] . W_fc[v, :] + b_fc[v]   (h from g_hT[0])
// ---------------------------------------------------------------------------
__global__ void __launch_bounds__(256, 1)
k_fc(const float* __restrict__ Wfc, const float* __restrict__ bfc,
     float* __restrict__ out)
{
    __shared__ float As_[16][128];
    __shared__ float Bs_[16][128];

    const int vBase = blockIdx.x * 128;
    const int tid   = threadIdx.x;
    const int ty    = tid >> 4;
    const int tx    = tid & 15;

    const float* __restrict__ hT = g_hT[0];

    float acc[8][8];
    #pragma unroll
    for (int i = 0; i < 8; i++)
        #pragma unroll
        for (int j = 0; j < 8; j++) acc[i][j] = 0.f;

    for (int k0 = 0; k0 < H; k0 += 16) {
        #pragma unroll
        for (int r = 0; r < 8; r++) {
            int idx = tid + 256 * r;
            int k = idx >> 7, m = idx & 127;
            As_[k][m] = hT[(k0 + k) * 128 + m];
        }
        #pragma unroll
        for (int r = 0; r < 8; r++) {
            int idx = tid + 256 * r;
            int vv = idx >> 4, k = idx & 15;
            int gv = vBase + vv;
            Bs_[k][vv] = (gv < V) ? Wfc[gv * H + k0 + k] : 0.f;
        }
        __syncthreads();

        #pragma unroll
        for (int k = 0; k < 16; k++) {
            float a[8], b[8];
            *(float4*)&a[0] = *(const float4*)&As_[k][ty * 8];
            *(float4*)&a[4] = *(const float4*)&As_[k][ty * 8 + 4];
            *(float4*)&b[0] = *(const float4*)&Bs_[k][tx * 8];
            *(float4*)&b[4] = *(const float4*)&Bs_[k][tx * 8 + 4];
            #pragma unroll
            for (int i = 0; i < 8; i++)
                #pragma unroll
                for (int j = 0; j < 8; j++)
                    acc[i][j] = fmaf(a[i], b[j], acc[i][j]);
        }
        __syncthreads();
    }

    #pragma unroll
    for (int i = 0; i < 8; i++) {
        int m = ty * 8 + i;
        #pragma unroll
        for (int j = 0; j < 8; j++) {
            int gv = vBase + tx * 8 + j;
            if (gv < V) out[m * V + gv] = acc[i][j] + bfc[gv];
        }
    }
}

// ---------------------------------------------------------------------------
extern "C" void kernel_launch(void* const* d_in, const int* in_sizes, int n_in,
                              void* d_out, int out_size)
{
    const int*   tokens  = (const int*)  d_in[0];
    const int*   lengths = (const int*)  d_in[1];
    const float* emb     = (const float*)d_in[2];
    const float* Wih     = (const float*)d_in[3];
    const float* Whh     = (const float*)d_in[4];
    const float* bih     = (const float*)d_in[5];
    const float* bhh     = (const float*)d_in[6];
    const float* Wfc     = (const float*)d_in[7];
    const float* bfc     = (const float*)d_in[8];
    float* out = (float*)d_out;

    const int smemBytes = (16384 + 8 * 2 * 8 * 132 + 8 * 16 * 132) * 4;
    static bool attrSet = false;
    if (!attrSet) {
        cudaFuncSetAttribute(k_lstm, cudaFuncAttributeMaxDynamicSharedMemorySize,
                             smemBytes);
        attrSet = true;
    }

    k_init<<<(H * B + 255) / 256, 256>>>(tokens);
    dim3 xg(16, 512);
    k_xproj<<<xg, 256>>>(Wih, bih, bhh, emb);
    for (int seg = 0; seg < 4; seg++) {
        k_lstm<<<NBLK, NTHR, smemBytes>>>(lengths, Whh,
                                          seg * (L / 4), (seg + 1) * (L / 4));
    }
    k_fc<<<(V + 127) / 128, 256>>>(Wfc, bfc, out);
}

// round 16
// speedup vs baseline: 1.2335x; 1.2335x over previous
#include <cuda_runtime.h>
#include <math.h>
#include <stdint.h>

// Problem constants
#define B 128
#define L 512
#define H 512
#define V 50000

#define NBLK 128
#define NTHR 512

typedef unsigned long long ull;

// ---------------------------------------------------------------------------
// Device globals (static scratch; no runtime allocation)
// ---------------------------------------------------------------------------
__device__ float    g_hT[2][H * B];       // transposed hidden state [k][b], x2
__device__ float    g_c[B * H];           // cell state (segment handoff)
__device__ int      g_tokT[L * B];        // transposed tokens [t][b]
__device__ unsigned g_arrive;             // grid barrier counter
__device__ float    g_xp[(long)L * 2048 * B];  // x_proj + biases: [t][grow][b]

// ---------------------------------------------------------------------------
__device__ __forceinline__ float2 unpackf2(ull v) {
    float2 r; asm("mov.b64 {%0, %1}, %2;" : "=f"(r.x), "=f"(r.y) : "l"(v));
    return r;
}
__device__ __forceinline__ void fma2(ull& d, ull a, ull b) {
    asm("fma.rn.f32x2 %0, %1, %2, %0;" : "+l"(d) : "l"(a), "l"(b));
}
__device__ __forceinline__ float sigf(float x) {
    return 1.f / (1.f + __expf(-x));
}
__device__ __forceinline__ uint32_t f2tf32(float x) {
    uint32_t r;
    asm("cvt.rna.tf32.f32 %0, %1;" : "=r"(r) : "f"(x));
    return r;
}

// ---------------------------------------------------------------------------
__global__ void k_init(const int* __restrict__ tokens) {
    int i = blockIdx.x * blockDim.x + threadIdx.x;
    if (i < H * B) { g_hT[0][i] = 0.f; g_hT[1][i] = 0.f; g_c[i] = 0.f; }
    if (i < L * B) {
        int t = i >> 7, b = i & 127;
        g_tokT[i] = tokens[b * L + t];
    }
    if (i == 0) g_arrive = 0u;
}

// ---------------------------------------------------------------------------
// x_proj GEMM via tf32 tensor cores (mma.sync.m16n8k8):
//   g_xp[t][grow][b] = Wih[grow,:].emb[tok[t][b],:] + bih[grow] + bhh[grow]
// Block = 128 grows x 128 batch, K=512 in 16 chunks of 32 k.
// 8 warps = 4 grow-strips (32) x 2 batch-strips (64); warp = 2m x 8n mma
// tiles. A/B staged in smem in fragment-pair layout: per row, per k8-group g,
// float2 slot c = (k=8g+c, k=8g+c+4) so every fragment is one LDS.64.
// ---------------------------------------------------------------------------
__global__ void __launch_bounds__(256, 2)
k_xproj(const float* __restrict__ Wih, const float* __restrict__ bih,
        const float* __restrict__ bhh, const float* __restrict__ emb)
{
    __shared__ uint32_t Asm[128 * 36];   // [row][g*8 + 2c + half]
    __shared__ uint32_t Bsm[128 * 36];   // [batch][g*8 + 2c + half]
    __shared__ float    bsum[128];
    __shared__ int      tok[128];

    const int gt   = blockIdx.x;         // grow tile 0..15
    const int t    = blockIdx.y;         // timestep 0..511
    const int tid  = threadIdx.x;
    const int warp = tid >> 5;
    const int lane = tid & 31;
    const int wr   = warp & 3;           // grow strip: rows [32wr, 32wr+32)
    const int wc   = warp >> 2;          // batch strip: cols [64wc, 64wc+64)
    const int gid  = lane >> 2;          // fragment group id (row/col)
    const int tig  = lane & 3;           // thread-in-group (k index)

    if (tid < 128) {
        tok[tid]  = g_tokT[t * 128 + tid];
        int grow  = gt * 128 + tid;
        bsum[tid] = bih[grow] + bhh[grow];
    }
    __syncthreads();

    float acc[2][8][4];
    #pragma unroll
    for (int m = 0; m < 2; m++)
        #pragma unroll
        for (int n = 0; n < 8; n++)
            #pragma unroll
            for (int j = 0; j < 4; j++) acc[m][n][j] = 0.f;

    for (int k0 = 0; k0 < 512; k0 += 32) {
        // ---- stage A (Wih) and B (emb gather), cvt to tf32, pair layout ----
        #pragma unroll
        for (int i = 0; i < 4; i++) {
            int id  = tid + 256 * i;
            int row = id >> 3, f = id & 7;
            int g = f >> 1, half = f & 1;
            {
                const float4 w4 = *(const float4*)(Wih + (gt * 128 + row) * 512
                                                   + k0 + 4 * f);
                uint32_t* dst = Asm + row * 36 + g * 8 + half;
                dst[0] = f2tf32(w4.x); dst[2] = f2tf32(w4.y);
                dst[4] = f2tf32(w4.z); dst[6] = f2tf32(w4.w);
            }
            {
                const float4 v4 = *(const float4*)(emb + (long)tok[row] * 512
                                                   + k0 + 4 * f);
                uint32_t* dst = Bsm + row * 36 + g * 8 + half;
                dst[0] = f2tf32(v4.x); dst[2] = f2tf32(v4.y);
                dst[4] = f2tf32(v4.z); dst[6] = f2tf32(v4.w);
            }
        }
        __syncthreads();

        // ---- compute: 4 k8-steps x (2m x 8n) mma ----
        #pragma unroll
        for (int g = 0; g < 4; g++) {
            uint32_t a[2][4];
            #pragma unroll
            for (int m = 0; m < 2; m++) {
                const uint32_t* pa = Asm + (wr * 32 + 16 * m + gid) * 36
                                   + g * 8 + 2 * tig;
                uint2 lo = *(const uint2*)pa;            // rows gid
                uint2 hi = *(const uint2*)(pa + 8 * 36); // rows gid+8
                a[m][0] = lo.x; a[m][2] = lo.y;
                a[m][1] = hi.x; a[m][3] = hi.y;
            }
            #pragma unroll
            for (int nt = 0; nt < 8; nt++) {
                const uint32_t* pb = Bsm + (wc * 64 + 8 * nt + gid) * 36
                                   + g * 8 + 2 * tig;
                uint2 bb = *(const uint2*)pb;            // b0, b1
                #pragma unroll
                for (int m = 0; m < 2; m++) {
                    asm volatile(
                        "mma.sync.aligned.m16n8k8.row.col.f32.tf32.tf32.f32 "
                        "{%0,%1,%2,%3}, {%4,%5,%6,%7}, {%8,%9}, {%0,%1,%2,%3};"
                        : "+f"(acc[m][nt][0]), "+f"(acc[m][nt][1]),
                          "+f"(acc[m][nt][2]), "+f"(acc[m][nt][3])
                        : "r"(a[m][0]), "r"(a[m][1]), "r"(a[m][2]), "r"(a[m][3]),
                          "r"(bb.x), "r"(bb.y));
                }
            }
        }
        __syncthreads();
    }

    // ---- epilogue: add biases, write g_xp ----
    float* outp = g_xp + (long)t * 262144 + (gt * 128) * 128;
    #pragma unroll
    for (int m = 0; m < 2; m++) {
        int row0 = wr * 32 + 16 * m + gid;
        float bias0 = bsum[row0];
        float bias1 = bsum[row0 + 8];
        #pragma unroll
        for (int nt = 0; nt < 8; nt++) {
            int col = wc * 64 + 8 * nt + 2 * tig;
            float2 lo = make_float2(acc[m][nt][0] + bias0,
                                    acc[m][nt][1] + bias0);
            float2 hi = make_float2(acc[m][nt][2] + bias1,
                                    acc[m][nt][3] + bias1);
            *(float2*)(outp + row0 * 128 + col)       = lo;
            *(float2*)(outp + (row0 + 8) * 128 + col) = hi;
        }
    }
}

// ---------------------------------------------------------------------------
// Persistent LSTM recurrence over t in [t0, t1). K = 512 (h half only).
// (verbatim R13 best: 4 K-sets x 4 batch-groups, ldcg->STS double buffer,
//  128-thread set barriers, cg-style grid barrier)
// ---------------------------------------------------------------------------
extern __shared__ float smem[];

__global__ void __launch_bounds__(NTHR, 1)
k_lstm(const int* __restrict__ lengths, const float* __restrict__ Whh,
       int t0, int t1)
{
    float* Wd = smem;                 // [512][32] dup (w,w) pairs = 16384 fl
    float* As = Wd + 16384;           // [4 sets][2 buf][16 k][132]
    float* Gs = As + 4 * 2 * 16 * 132; // [4 sets][16][132] partials

    const int tid  = threadIdx.x;
    const int bx   = blockIdx.x;
    const int w    = tid >> 5;
    const int lane = tid & 31;

    // ---- dup-weight table (W_hh only, K=512) ----
    for (int idx = tid; idx < 16 * 512; idx += NTHR) {
        int k  = idx >> 4;
        int lr = idx & 15;
        int g = lr >> 2, cc = lr & 3;
        int grow = g * 512 + bx * 4 + cc;
        float wv = Whh[grow * 512 + k];
        Wd[k * 32 + 2 * lr]     = wv;
        Wd[k * 32 + 2 * lr + 1] = wv;
    }

    // ---- warp roles ----
    const int set = w & 3;            // K-set: k in [128set, 128set+128)
    const int w4  = w >> 2;           // 0..3: batch group [32w4, 32w4+32)
    const int kb0 = 128 * set;
    float* AsS = As + set * (2 * 16 * 132);

    const int r4 = lane & 3;          // rows 4r4..4r4+3
    const int bq = lane >> 2;         // 0..7: 4-batch quad within group

    // ---- pointwise roles ----
    const int pb = tid >> 2;          // batch 0..127
    const int pc = tid & 3;
    const int hcol = bx * 4 + pc;
    const int len  = lengths[pb];
    float c_reg = g_c[pb * H + hcol];
    float h_reg = g_hT[t0 & 1][hcol * 128 + pb];

    __syncthreads();

    for (int t = t0; t < t1; t++) {
        const int rb = t & 1, wb = rb ^ 1;
        const float* __restrict__ hT = g_hT[rb];

        // prefetch x_proj for my (pb, pc)
        float xq[4];
        #pragma unroll
        for (int g = 0; g < 4; g++)
            xq[g] = __ldg(g_xp + (long)t * 262144
                          + (g * 512 + bx * 4 + pc) * 128 + pb);

        ull acc[8];
        #pragma unroll
        for (int i = 0; i < 8; i++) acc[i] = 0ull;

        float4 v4[4];

        // ---- stage chunk 0 (k rows kb0+4w4+m, all 128 b) — L2-coherent ----
        #pragma unroll
        for (int m = 0; m < 4; m++) {
            int kg = kb0 + 4 * w4 + m;
            v4[m] = __ldcg((const float4*)(hT + kg * 128 + 4 * lane));
        }
        #pragma unroll
        for (int m = 0; m < 4; m++)
            *(float4*)(AsS + (4 * w4 + m) * 132 + 4 * lane) = v4[m];
        asm volatile("bar.sync %0, %1;" :: "r"(1 + set), "r"(128) : "memory");

        for (int c = 0; c < 8; c++) {
            // prefetch chunk c+1
            if (c < 7) {
                #pragma unroll
                for (int m = 0; m < 4; m++) {
                    int kg = kb0 + 16 * (c + 1) + 4 * w4 + m;
                    v4[m] = __ldcg((const float4*)(hT + kg * 128 + 4 * lane));
                }
            }

            // compute chunk c (16 k)
            {
                const float* Ab = AsS + (c & 1) * (16 * 132) + 32 * w4 + 4 * bq;
                const float* Wk = Wd + (kb0 + 16 * c) * 32 + 8 * r4;
                #pragma unroll
                for (int k = 0; k < 16; k++) {
                    ulonglong2 a   = *(const ulonglong2*)(Ab + k * 132);
                    ulonglong2 w01 = *(const ulonglong2*)(Wk + k * 32);
                    ulonglong2 w23 = *(const ulonglong2*)(Wk + k * 32 + 4);
                    fma2(acc[0], a.x, w01.x);  fma2(acc[1], a.y, w01.x);
                    fma2(acc[2], a.x, w01.y);  fma2(acc[3], a.y, w01.y);
                    fma2(acc[4], a.x, w23.x);  fma2(acc[5], a.y, w23.x);
                    fma2(acc[6], a.x, w23.y);  fma2(acc[7], a.y, w23.y);
                }
            }

            // commit prefetched chunk
            if (c < 7) {
                float* dst = AsS + ((c + 1) & 1) * (16 * 132);
                #pragma unroll
                for (int m = 0; m < 4; m++)
                    *(float4*)(dst + (4 * w4 + m) * 132 + 4 * lane) = v4[m];
            }
            asm volatile("bar.sync %0, %1;" :: "r"(1 + set), "r"(128) : "memory");
        }

        // ---- park partial tiles ----
        #pragma unroll
        for (int r = 0; r < 4; r++) {
            ulonglong2 pr; pr.x = acc[2 * r]; pr.y = acc[2 * r + 1];
            *(ulonglong2*)(Gs + set * (16 * 132) + (4 * r4 + r) * 132
                           + 32 * w4 + 4 * bq) = pr;
        }
        __syncthreads();

        // ---- reduce 4 K-set partials + x_proj + gates ----
        {
            float xi = xq[0], xf = xq[1], xg = xq[2], xo = xq[3];
            #pragma unroll
            for (int s = 0; s < 4; s++) {
                const float* P = Gs + s * (16 * 132);
                xi += P[(0 + pc)  * 132 + pb];
                xf += P[(4 + pc)  * 132 + pb];
                xg += P[(8 + pc)  * 132 + pb];
                xo += P[(12 + pc) * 132 + pb];
            }
            if (t < len) {
                float ig = sigf(xi), fg = sigf(xf), og = sigf(xo);
                float gg = 2.f * sigf(2.f * xg) - 1.f;
                c_reg = fg * c_reg + ig * gg;
                h_reg = og * (2.f * sigf(2.f * c_reg) - 1.f);
            }
            __stcg(&g_hT[wb][hcol * 128 + pb], h_reg);
        }

        // ---- grid barrier: cg-style, tid0 only (fence + arrive + poll) ----
        __syncthreads();
        if (tid == 0) {
            asm volatile("fence.acq_rel.gpu;" ::: "memory");
            atomicAdd(&g_arrive, 1u);
            unsigned target = (unsigned)NBLK * (unsigned)(t + 1);
            unsigned cur;
            do {
                asm volatile("ld.acquire.gpu.global.u32 %0, [%1];"
                             : "=r"(cur) : "l"(&g_arrive));
            } while (cur < target);
        }
        __syncthreads();
    }

    // ---- segment handoff ----
    g_c[pb * H + hcol] = c_reg;
}

// ---------------------------------------------------------------------------
// FC: out[b, v] = h_final[b, :] . W_fc[v, :] + b_fc[v]   (h from g_hT[0])
// ---------------------------------------------------------------------------
__global__ void __launch_bounds__(256, 1)
k_fc(const float* __restrict__ Wfc, const float* __restrict__ bfc,
     float* __restrict__ out)
{
    __shared__ float As_[16][128];
    __shared__ float Bs_[16][128];

    const int vBase = blockIdx.x * 128;
    const int tid   = threadIdx.x;
    const int ty    = tid >> 4;
    const int tx    = tid & 15;

    const float* __restrict__ hT = g_hT[0];

    float acc[8][8];
    #pragma unroll
    for (int i = 0; i < 8; i++)
        #pragma unroll
        for (int j = 0; j < 8; j++) acc[i][j] = 0.f;

    for (int k0 = 0; k0 < H; k0 += 16) {
        #pragma unroll
        for (int r = 0; r < 8; r++) {
            int idx = tid + 256 * r;
            int k = idx >> 7, m = idx & 127;
            As_[k][m] = hT[(k0 + k) * 128 + m];       // coalesced
        }
        #pragma unroll
        for (int r = 0; r < 8; r++) {
            int idx = tid + 256 * r;
            int vv = idx >> 4, k = idx & 15;
            int gv = vBase + vv;
            Bs_[k][vv] = (gv < V) ? Wfc[gv * H + k0 + k] : 0.f;
        }
        __syncthreads();

        #pragma unroll
        for (int k = 0; k < 16; k++) {
            float a[8], b[8];
            *(float4*)&a[0] = *(const float4*)&As_[k][ty * 8];
            *(float4*)&a[4] = *(const float4*)&As_[k][ty * 8 + 4];
            *(float4*)&b[0] = *(const float4*)&Bs_[k][tx * 8];
            *(float4*)&b[4] = *(const float4*)&Bs_[k][tx * 8 + 4];
            #pragma unroll
            for (int i = 0; i < 8; i++)
                #pragma unroll
                for (int j = 0; j < 8; j++)
                    acc[i][j] = fmaf(a[i], b[j], acc[i][j]);
        }
        __syncthreads();
    }

    #pragma unroll
    for (int i = 0; i < 8; i++) {
        int m = ty * 8 + i;
        #pragma unroll
        for (int j = 0; j < 8; j++) {
            int gv = vBase + tx * 8 + j;
            if (gv < V) out[m * V + gv] = acc[i][j] + bfc[gv];
        }
    }
}

// ---------------------------------------------------------------------------
extern "C" void kernel_launch(void* const* d_in, const int* in_sizes, int n_in,
                              void* d_out, int out_size)
{
    const int*   tokens  = (const int*)  d_in[0];
    const int*   lengths = (const int*)  d_in[1];
    const float* emb     = (const float*)d_in[2];
    const float* Wih     = (const float*)d_in[3];
    const float* Whh     = (const float*)d_in[4];
    const float* bih     = (const float*)d_in[5];
    const float* bhh     = (const float*)d_in[6];
    const float* Wfc     = (const float*)d_in[7];
    const float* bfc     = (const float*)d_in[8];
    float* out = (float*)d_out;

    const int smemBytes = (16384 + 4 * 2 * 16 * 132 + 4 * 16 * 132) * 4;
    static bool attrSet = false;
    if (!attrSet) {
        cudaFuncSetAttribute(k_lstm, cudaFuncAttributeMaxDynamicSharedMemorySize,
                             smemBytes);
        attrSet = true;
    }

    k_init<<<(H * B + 255) / 256, 256>>>(tokens);
    dim3 xg(16, 512);
    k_xproj<<<xg, 256>>>(Wih, bih, bhh, emb);
    for (int seg = 0; seg < 4; seg++) {
        k_lstm<<<NBLK, NTHR, smemBytes>>>(lengths, Whh,
                                          seg * (L / 4), (seg + 1) * (L / 4));
    }
    k_fc<<<(V + 127) / 128, 256>>>(Wfc, bfc, out);
}

// round 17
// speedup vs baseline: 2.0040x; 1.6247x over previous
#include <cuda_runtime.h>
#include <math.h>
#include <stdint.h>

// Problem constants
#define B 128
#define L 512
#define H 512
#define V 50000

#define NBLK 128
#define NTHR 512

typedef unsigned long long ull;

// ---------------------------------------------------------------------------
// Device globals (static scratch; no runtime allocation)
// ---------------------------------------------------------------------------
__device__ float    g_hT[2][H * B];       // transposed hidden state [k][b], x2
__device__ float    g_c[B * H];           // cell state (segment handoff)
__device__ int      g_tokT[L * B];        // transposed tokens [t][b]
__device__ unsigned g_arrive;             // grid barrier counter
__device__ float    g_xp[(long)L * 2048 * B];  // x_proj + biases: [t][grow][b]

// ---------------------------------------------------------------------------
__device__ __forceinline__ float2 unpackf2(ull v) {
    float2 r; asm("mov.b64 {%0, %1}, %2;" : "=f"(r.x), "=f"(r.y) : "l"(v));
    return r;
}
__device__ __forceinline__ void fma2(ull& d, ull a, ull b) {
    asm("fma.rn.f32x2 %0, %1, %2, %0;" : "+l"(d) : "l"(a), "l"(b));
}
__device__ __forceinline__ float sigf(float x) {
    return 1.f / (1.f + __expf(-x));
}
__device__ __forceinline__ uint32_t f2tf32(float x) {
    uint32_t r;
    asm("cvt.rna.tf32.f32 %0, %1;" : "=r"(r) : "f"(x));
    return r;
}
__device__ __forceinline__ void mma_tf32(float* c, uint32_t a0, uint32_t a1,
                                         uint32_t a2, uint32_t a3,
                                         uint32_t b0, uint32_t b1) {
    asm volatile(
        "mma.sync.aligned.m16n8k8.row.col.f32.tf32.tf32.f32 "
        "{%0,%1,%2,%3}, {%4,%5,%6,%7}, {%8,%9}, {%0,%1,%2,%3};"
        : "+f"(c[0]), "+f"(c[1]), "+f"(c[2]), "+f"(c[3])
        : "r"(a0), "r"(a1), "r"(a2), "r"(a3), "r"(b0), "r"(b1));
}

// ---------------------------------------------------------------------------
__global__ void k_init(const int* __restrict__ tokens) {
    int i = blockIdx.x * blockDim.x + threadIdx.x;
    if (i < H * B) { g_hT[0][i] = 0.f; g_hT[1][i] = 0.f; g_c[i] = 0.f; }
    if (i < L * B) {
        int t = i >> 7, b = i & 127;
        g_tokT[i] = tokens[b * L + t];
    }
    if (i == 0) g_arrive = 0u;
}

// ---------------------------------------------------------------------------
// x_proj GEMM via tf32 tensor cores (verbatim R16 passing version)
// ---------------------------------------------------------------------------
__global__ void __launch_bounds__(256, 2)
k_xproj(const float* __restrict__ Wih, const float* __restrict__ bih,
        const float* __restrict__ bhh, const float* __restrict__ emb)
{
    __shared__ uint32_t Asm[128 * 36];
    __shared__ uint32_t Bsm[128 * 36];
    __shared__ float    bsum[128];
    __shared__ int      tok[128];

    const int gt   = blockIdx.x;
    const int t    = blockIdx.y;
    const int tid  = threadIdx.x;
    const int warp = tid >> 5;
    const int lane = tid & 31;
    const int wr   = warp & 3;
    const int wc   = warp >> 2;
    const int gid  = lane >> 2;
    const int tig  = lane & 3;

    if (tid < 128) {
        tok[tid]  = g_tokT[t * 128 + tid];
        int grow  = gt * 128 + tid;
        bsum[tid] = bih[grow] + bhh[grow];
    }
    __syncthreads();

    float acc[2][8][4];
    #pragma unroll
    for (int m = 0; m < 2; m++)
        #pragma unroll
        for (int n = 0; n < 8; n++)
            #pragma unroll
            for (int j = 0; j < 4; j++) acc[m][n][j] = 0.f;

    for (int k0 = 0; k0 < 512; k0 += 32) {
        #pragma unroll
        for (int i = 0; i < 4; i++) {
            int id  = tid + 256 * i;
            int row = id >> 3, f = id & 7;
            int g = f >> 1, half = f & 1;
            {
                const float4 w4 = *(const float4*)(Wih + (gt * 128 + row) * 512
                                                   + k0 + 4 * f);
                uint32_t* dst = Asm + row * 36 + g * 8 + half;
                dst[0] = f2tf32(w4.x); dst[2] = f2tf32(w4.y);
                dst[4] = f2tf32(w4.z); dst[6] = f2tf32(w4.w);
            }
            {
                const float4 v4 = *(const float4*)(emb + (long)tok[row] * 512
                                                   + k0 + 4 * f);
                uint32_t* dst = Bsm + row * 36 + g * 8 + half;
                dst[0] = f2tf32(v4.x); dst[2] = f2tf32(v4.y);
                dst[4] = f2tf32(v4.z); dst[6] = f2tf32(v4.w);
            }
        }
        __syncthreads();

        #pragma unroll
        for (int g = 0; g < 4; g++) {
            uint32_t a[2][4];
            #pragma unroll
            for (int m = 0; m < 2; m++) {
                const uint32_t* pa = Asm + (wr * 32 + 16 * m + gid) * 36
                                   + g * 8 + 2 * tig;
                uint2 lo = *(const uint2*)pa;
                uint2 hi = *(const uint2*)(pa + 8 * 36);
                a[m][0] = lo.x; a[m][2] = lo.y;
                a[m][1] = hi.x; a[m][3] = hi.y;
            }
            #pragma unroll
            for (int nt = 0; nt < 8; nt++) {
                const uint32_t* pb = Bsm + (wc * 64 + 8 * nt + gid) * 36
                                   + g * 8 + 2 * tig;
                uint2 bb = *(const uint2*)pb;
                #pragma unroll
                for (int m = 0; m < 2; m++)
                    mma_tf32(acc[m][nt], a[m][0], a[m][1], a[m][2], a[m][3],
                             bb.x, bb.y);
            }
        }
        __syncthreads();
    }

    float* outp = g_xp + (long)t * 262144 + (gt * 128) * 128;
    #pragma unroll
    for (int m = 0; m < 2; m++) {
        int row0 = wr * 32 + 16 * m + gid;
        float bias0 = bsum[row0];
        float bias1 = bsum[row0 + 8];
        #pragma unroll
        for (int nt = 0; nt < 8; nt++) {
            int col = wc * 64 + 8 * nt + 2 * tig;
            float2 lo = make_float2(acc[m][nt][0] + bias0,
                                    acc[m][nt][1] + bias0);
            float2 hi = make_float2(acc[m][nt][2] + bias1,
                                    acc[m][nt][3] + bias1);
            *(float2*)(outp + row0 * 128 + col)       = lo;
            *(float2*)(outp + (row0 + 8) * 128 + col) = hi;
        }
    }
}

// ---------------------------------------------------------------------------
// Persistent LSTM recurrence, tf32 tensor-core edition. t in [t0, t1).
// Block bx owns h-cols [4bx,4bx+4) -> 16 gate rows. GEMM per step:
//   C[m=128 batch][n=16 gate rows] = hT^T[128 x 512k] @ Whh_slice^T
// 16 warps = 2 n-halves (8 rows) x 4 k-ranges (128 k) x 2 m-halves (64 b).
// W_hh B-fragments (RNA tf32) live in 32 regs/warp-thread permanently.
// h staged per k-range as tf32 [k][b] (stride 136 -> conflict-free LDS.32
// fragment gathers), double-buffered 16-k chunks, 128-thread set barriers.
// 4 k-range partials reduced in smem; pointwise + grid barrier as R13.
// ---------------------------------------------------------------------------
extern __shared__ float smem[];

__global__ void __launch_bounds__(NTHR, 1)
k_lstm(const int* __restrict__ lengths, const float* __restrict__ Whh,
       int t0, int t1)
{
    float* hs = smem;                  // [4 kr][2 buf][16 k][136] tf32 bits
    float* Gs = hs + 4 * 2 * 16 * 136; // [4 kr][16 rows][132] partials

    const int tid  = threadIdx.x;
    const int bx   = blockIdx.x;
    const int w    = tid >> 5;
    const int lane = tid & 31;

    const int nh  = w & 1;             // gate-row half: rows [8nh, 8nh+8)
    const int kr  = (w >> 1) & 3;      // k-range: [128kr, 128kr+128)
    const int mh  = w >> 3;            // batch half: [64mh, 64mh+64)
    const int sw  = nh * 2 + mh;       // staging slot within set (0..3)
    const int gid = lane >> 2;
    const int tig = lane & 3;
    const int kb0 = kr * 128;
    float* hsS = hs + kr * (2 * 16 * 136);

    // ---- permanent W_hh B-fragments: 16 k-steps x (k, k+4) ----
    uint32_t wreg[16][2];
    {
        int lr   = nh * 8 + gid;
        int grow = (lr >> 2) * 512 + bx * 4 + (lr & 3);
        const float* wp = Whh + grow * 512 + kb0;
        #pragma unroll
        for (int s = 0; s < 16; s++) {
            wreg[s][0] = f2tf32(wp[s * 8 + tig]);
            wreg[s][1] = f2tf32(wp[s * 8 + tig + 4]);
        }
    }

    // ---- pointwise roles ----
    const int pb = tid >> 2;           // batch 0..127
    const int pc = tid & 3;
    const int hcol = bx * 4 + pc;
    const int len  = lengths[pb];
    float c_reg = g_c[pb * H + hcol];
    float h_reg = g_hT[t0 & 1][hcol * 128 + pb];

    __syncthreads();

    for (int t = t0; t < t1; t++) {
        const int rb = t & 1, wb = rb ^ 1;
        const float* __restrict__ hT = g_hT[rb];

        // prefetch x_proj for my (pb, pc)
        float xq[4];
        #pragma unroll
        for (int g = 0; g < 4; g++)
            xq[g] = __ldg(g_xp + (long)t * 262144
                          + (g * 512 + bx * 4 + pc) * 128 + pb);

        float acc[4][4];
        #pragma unroll
        for (int mt = 0; mt < 4; mt++)
            #pragma unroll
            for (int j = 0; j < 4; j++) acc[mt][j] = 0.f;

        uint4 sv[4];

        // ---- stage chunk 0: k rows kb0 + 4sw + m, all 128 b, cvt tf32 ----
        #pragma unroll
        for (int m = 0; m < 4; m++) {
            float4 v = __ldcg((const float4*)(hT + (kb0 + 4 * sw + m) * 128
                                              + 4 * lane));
            sv[m] = make_uint4(f2tf32(v.x), f2tf32(v.y),
                               f2tf32(v.z), f2tf32(v.w));
        }
        #pragma unroll
        for (int m = 0; m < 4; m++)
            *(uint4*)(hsS + (4 * sw + m) * 136 + 4 * lane) = sv[m];
        asm volatile("bar.sync %0, %1;" :: "r"(1 + kr), "r"(128) : "memory");

        for (int c = 0; c < 8; c++) {
            // prefetch chunk c+1 (LDG + cvt)
            if (c < 7) {
                #pragma unroll
                for (int m = 0; m < 4; m++) {
                    int kg = kb0 + 16 * (c + 1) + 4 * sw + m;
                    float4 v = __ldcg((const float4*)(hT + kg * 128 + 4 * lane));
                    sv[m] = make_uint4(f2tf32(v.x), f2tf32(v.y),
                                       f2tf32(v.z), f2tf32(v.w));
                }
            }

            // compute chunk c: 2 k-steps x 4 m-tiles
            {
                const uint32_t* Ab = (const uint32_t*)(hsS + (c & 1) * (16 * 136));
                #pragma unroll
                for (int s = 0; s < 2; s++) {
                    const int ks = c * 2 + s;
                    const uint32_t b0 = wreg[ks][0], b1 = wreg[ks][1];
                    const uint32_t* pas = Ab + (s * 8 + tig) * 136
                                        + mh * 64 + gid;
                    #pragma unroll
                    for (int mt = 0; mt < 4; mt++) {
                        const uint32_t* pa = pas + mt * 16;
                        uint32_t a0 = pa[0];
                        uint32_t a1 = pa[8];
                        uint32_t a2 = pa[4 * 136];
                        uint32_t a3 = pa[4 * 136 + 8];
                        mma_tf32(acc[mt], a0, a1, a2, a3, b0, b1);
                    }
                }
            }

            // commit prefetched chunk
            if (c < 7) {
                float* dst = hsS + ((c + 1) & 1) * (16 * 136);
                #pragma unroll
                for (int m = 0; m < 4; m++)
                    *(uint4*)(dst + (4 * sw + m) * 136 + 4 * lane) = sv[m];
            }
            asm volatile("bar.sync %0, %1;" :: "r"(1 + kr), "r"(128) : "memory");
        }

        // ---- park partial tiles: Gs[kr][gate row][batch] ----
        {
            float* gp = Gs + kr * (16 * 132);
            const int row0 = nh * 8 + 2 * tig;
            #pragma unroll
            for (int mt = 0; mt < 4; mt++) {
                int col = mh * 64 + mt * 16 + gid;
                gp[row0 * 132 + col]           = acc[mt][0];
                gp[(row0 + 1) * 132 + col]     = acc[mt][1];
                gp[row0 * 132 + col + 8]       = acc[mt][2];
                gp[(row0 + 1) * 132 + col + 8] = acc[mt][3];
            }
        }
        __syncthreads();

        // ---- reduce 4 k-range partials + x_proj + gates ----
        {
            float xi = xq[0], xf = xq[1], xg = xq[2], xo = xq[3];
            #pragma unroll
            for (int s = 0; s < 4; s++) {
                const float* P = Gs + s * (16 * 132);
                xi += P[(0 + pc)  * 132 + pb];
                xf += P[(4 + pc)  * 132 + pb];
                xg += P[(8 + pc)  * 132 + pb];
                xo += P[(12 + pc) * 132 + pb];
            }
            if (t < len) {
                float ig = sigf(xi), fg = sigf(xf), og = sigf(xo);
                float gg = 2.f * sigf(2.f * xg) - 1.f;
                c_reg = fg * c_reg + ig * gg;
                h_reg = og * (2.f * sigf(2.f * c_reg) - 1.f);
            }
            __stcg(&g_hT[wb][hcol * 128 + pb], h_reg);
        }

        // ---- grid barrier: cg-style, tid0 only ----
        __syncthreads();
        if (tid == 0) {
            asm volatile("fence.acq_rel.gpu;" ::: "memory");
            atomicAdd(&g_arrive, 1u);
            unsigned target = (unsigned)NBLK * (unsigned)(t + 1);
            unsigned cur;
            do {
                asm volatile("ld.acquire.gpu.global.u32 %0, [%1];"
                             : "=r"(cur) : "l"(&g_arrive));
            } while (cur < target);
        }
        __syncthreads();
    }

    // ---- segment handoff ----
    g_c[pb * H + hcol] = c_reg;
}

// ---------------------------------------------------------------------------
// FC: out[b, v] = h_final[b, :] . W_fc[v, :] + b_fc[v]   (h from g_hT[0])
// ---------------------------------------------------------------------------
__global__ void __launch_bounds__(256, 1)
k_fc(const float* __restrict__ Wfc, const float* __restrict__ bfc,
     float* __restrict__ out)
{
    __shared__ float As_[16][128];
    __shared__ float Bs_[16][128];

    const int vBase = blockIdx.x * 128;
    const int tid   = threadIdx.x;
    const int ty    = tid >> 4;
    const int tx    = tid & 15;

    const float* __restrict__ hT = g_hT[0];

    float acc[8][8];
    #pragma unroll
    for (int i = 0; i < 8; i++)
        #pragma unroll
        for (int j = 0; j < 8; j++) acc[i][j] = 0.f;

    for (int k0 = 0; k0 < H; k0 += 16) {
        #pragma unroll
        for (int r = 0; r < 8; r++) {
            int idx = tid + 256 * r;
            int k = idx >> 7, m = idx & 127;
            As_[k][m] = hT[(k0 + k) * 128 + m];
        }
        #pragma unroll
        for (int r = 0; r < 8; r++) {
            int idx = tid + 256 * r;
            int vv = idx >> 4, k = idx & 15;
            int gv = vBase + vv;
            Bs_[k][vv] = (gv < V) ? Wfc[gv * H + k0 + k] : 0.f;
        }
        __syncthreads();

        #pragma unroll
        for (int k = 0; k < 16; k++) {
            float a[8], b[8];
            *(float4*)&a[0] = *(const float4*)&As_[k][ty * 8];
            *(float4*)&a[4] = *(const float4*)&As_[k][ty * 8 + 4];
            *(float4*)&b[0] = *(const float4*)&Bs_[k][tx * 8];
            *(float4*)&b[4] = *(const float4*)&Bs_[k][tx * 8 + 4];
            #pragma unroll
            for (int i = 0; i < 8; i++)
                #pragma unroll
                for (int j = 0; j < 8; j++)
                    acc[i][j] = fmaf(a[i], b[j], acc[i][j]);
        }
        __syncthreads();
    }

    #pragma unroll
    for (int i = 0; i < 8; i++) {
        int m = ty * 8 + i;
        #pragma unroll
        for (int j = 0; j < 8; j++) {
            int gv = vBase + tx * 8 + j;
            if (gv < V) out[m * V + gv] = acc[i][j] + bfc[gv];
        }
    }
}

// ---------------------------------------------------------------------------
extern "C" void kernel_launch(void* const* d_in, const int* in_sizes, int n_in,
                              void* d_out, int out_size)
{
    const int*   tokens  = (const int*)  d_in[0];
    const int*   lengths = (const int*)  d_in[1];
    const float* emb     = (const float*)d_in[2];
    const float* Wih     = (const float*)d_in[3];
    const float* Whh     = (const float*)d_in[4];
    const float* bih     = (const float*)d_in[5];
    const float* bhh     = (const float*)d_in[6];
    const float* Wfc     = (const float*)d_in[7];
    const float* bfc     = (const float*)d_in[8];
    float* out = (float*)d_out;

    const int smemBytes = (4 * 2 * 16 * 136 + 4 * 16 * 132) * 4;
    static bool attrSet = false;
    if (!attrSet) {
        cudaFuncSetAttribute(k_lstm, cudaFuncAttributeMaxDynamicSharedMemorySize,
                             smemBytes);
        attrSet = true;
    }

    k_init<<<(H * B + 255) / 256, 256>>>(tokens);
    dim3 xg(16, 512);
    k_xproj<<<xg, 256>>>(Wih, bih, bhh, emb);
    for (int seg = 0; seg < 4; seg++) {
        k_lstm<<<NBLK, NTHR, smemBytes>>>(lengths, Whh,
                                          seg * (L / 4), (seg + 1) * (L / 4));
    }
    k_fc<<<(V + 127) / 128, 256>>>(Wfc, bfc, out);
}